// round 4
// baseline (speedup 1.0000x reference)
#include <cuda_runtime.h>
#include <cuda_fp16.h>
#include <cstdint>

// Problem constants (fixed-shape problem: H=8, MH=8, N_NODES=500000)
#define H_DIM 8
#define MH_DIM 8
#define FEAT 64              // H*MH per sign
#define REC 128              // 2 signs * FEAT values per node record
#define MAX_NODES 500000
#define TILE_N 128           // nodes per transpose block

// Node-major scratch in fp16: [node][sign][h][mh], 256B per node,
// deg-normalization folded in. uint4 type guarantees 16B alignment for the
// vectorized gather loads.
__device__ uint4 g_pk_raw[(size_t)MAX_NODES * REC / 8];

// ---------------------------------------------------------------------------
// Kernel 1: transpose [s][h][mh][N] (feature-major) -> [N][s][h][mh] fp16,
// multiplying by 1/max(deg,1) on the fly.
// Block: 256 threads, tile of 128 nodes x 128 features.
// Load phase: float4 along node axis (512B per warp-row), convert+scale to
// fp16 directly into smem. Write phase: uint4 smem reads -> uint4 gmem stores
// (each warp writes 512B contiguous).
// ---------------------------------------------------------------------------
__global__ __launch_bounds__(256) void transpose_fold_kernel(
    const float* __restrict__ phi_pos,
    const float* __restrict__ phi_neg,
    const float* __restrict__ deg_pos,
    const float* __restrict__ deg_neg,
    int n_nodes)
{
    // stride 136 halves = 272B = 17*16B -> every row base stays 16B-aligned
    __shared__ __align__(16) __half tile[TILE_N][REC + 8];
    __shared__ float inv[2][TILE_N][H_DIM];   // 1/max(deg,1)

    const int k0 = blockIdx.x * TILE_N;
    const int t  = threadIdx.x;
    const bool full = (k0 + TILE_N <= n_nodes) && ((n_nodes & 3) == 0);

    // ---- inv table: 2*128*8 = 2048 values, contiguous gmem reads ----
    #pragma unroll
    for (int it = 0; it < 8; ++it) {
        int idx  = t + it * 256;            // s*1024 + node*8 + h
        int s    = idx >> 10;
        int rem  = idx & 1023;
        int node = rem >> 3;
        int h    = rem & 7;
        int k    = k0 + node;
        float d  = 1.0f;
        if (k < n_nodes) {
            const float* dp = s ? deg_neg : deg_pos;
            d = dp[(size_t)k * H_DIM + h];
        }
        inv[s][node][h] = 1.0f / fmaxf(d, 1.0f);
    }
    __syncthreads();   // inv must be ready before the scaled-convert loads

    // ---- main load: 128 feature rows x 32 float4 groups (128 nodes) ----
    if (full) {
        #pragma unroll
        for (int it = 0; it < 16; ++it) {
            int l = t + it * 256;
            int r = l >> 5;                 // feature row 0..127
            int g = l & 31;                 // node group (4 nodes)
            int s = r >> 6;
            int f = r & 63;                 // h*8 + mh
            int h = f >> 3;
            const float* src = s ? phi_neg : phi_pos;
            float4 v = __ldg(reinterpret_cast<const float4*>(
                src + (size_t)f * n_nodes + k0 + 4 * g));
            int n0 = 4 * g;
            tile[n0 + 0][r] = __float2half_rn(v.x * inv[s][n0 + 0][h]);
            tile[n0 + 1][r] = __float2half_rn(v.y * inv[s][n0 + 1][h]);
            tile[n0 + 2][r] = __float2half_rn(v.z * inv[s][n0 + 2][h]);
            tile[n0 + 3][r] = __float2half_rn(v.w * inv[s][n0 + 3][h]);
        }
    } else {
        // scalar fallback for the (single) partial tile
        #pragma unroll
        for (int it = 0; it < 64; ++it) {
            int l  = t + it * 256;          // 16384 = 128 rows * 128 nodes
            int r  = l >> 7;
            int kk = l & 127;
            int k  = k0 + kk;
            int s  = r >> 6;
            int f  = r & 63;
            int h  = f >> 3;
            float v = 0.0f;
            if (k < n_nodes) {
                const float* src = s ? phi_neg : phi_pos;
                v = __ldg(src + (size_t)f * n_nodes + k);
            }
            tile[kk][r] = __float2half_rn(v * inv[s][kk][h]);
        }
    }
    __syncthreads();

    // ---- write: 128 nodes * 16 uint4 chunks = 2048 stores ----
    #pragma unroll
    for (int it = 0; it < 8; ++it) {
        int l    = t + it * 256;
        int node = l >> 4;
        int c    = l & 15;                  // 16B chunk within record
        int k    = k0 + node;
        if (k < n_nodes) {
            uint4 val = *reinterpret_cast<const uint4*>(&tile[node][c * 8]);
            g_pk_raw[(size_t)k * (REC / 8) + c] = val;
        }
    }
}

// ---------------------------------------------------------------------------
// Kernel 2: gather + dot. 8 threads per query; thread j handles head j for
// both signs. Gathers are 16B uint4 loads from a 256B-contiguous fp16 record.
// out layout: [pos: nq*8][neg: nq*8]
// ---------------------------------------------------------------------------
__global__ __launch_bounds__(256) void gather_dot_kernel(
    const float* __restrict__ q_phi,
    const int*   __restrict__ k_indices,
    float* __restrict__ out,
    int nq)
{
    int t = blockIdx.x * blockDim.x + threadIdx.x;
    int i = t >> 3;
    if (i >= nq) return;
    int h = t & 7;

    int k = __ldg(k_indices + i);  // broadcast across the 8-thread group

    const float4* qp = reinterpret_cast<const float4*>(
        q_phi + (size_t)i * FEAT + h * MH_DIM);
    float4 q0 = __ldg(qp);
    float4 q1 = __ldg(qp + 1);

    // Record = 16 uint4 (256B). pos: chunks [0..7], neg: chunks [8..15].
    const uint4* rec = g_pk_raw + (size_t)k * (REC / 8);
    uint4 pr = __ldg(rec + h);
    uint4 nr = __ldg(rec + 8 + h);

    const __half2* ph = reinterpret_cast<const __half2*>(&pr);
    const __half2* nh = reinterpret_cast<const __half2*>(&nr);

    float2 p0 = __half22float2(ph[0]);
    float2 p1 = __half22float2(ph[1]);
    float2 p2 = __half22float2(ph[2]);
    float2 p3 = __half22float2(ph[3]);
    float2 n0 = __half22float2(nh[0]);
    float2 n1 = __half22float2(nh[1]);
    float2 n2 = __half22float2(nh[2]);
    float2 n3 = __half22float2(nh[3]);

    float dp = q0.x * p0.x + q0.y * p0.y + q0.z * p1.x + q0.w * p1.y
             + q1.x * p2.x + q1.y * p2.y + q1.z * p3.x + q1.w * p3.y;
    float dn = q0.x * n0.x + q0.y * n0.y + q0.z * n1.x + q0.w * n1.y
             + q1.x * n2.x + q1.y * n2.y + q1.z * n3.x + q1.w * n3.y;

    out[(size_t)i * H_DIM + h] = dp;
    out[(size_t)nq * H_DIM + (size_t)i * H_DIM + h] = dn;
}

extern "C" void kernel_launch(void* const* d_in, const int* in_sizes, int n_in,
                              void* d_out, int out_size)
{
    const float* q_phi   = (const float*)d_in[0];
    const float* phi_pos = (const float*)d_in[1];
    const float* phi_neg = (const float*)d_in[2];
    const float* deg_pos = (const float*)d_in[3];
    const float* deg_neg = (const float*)d_in[4];
    const int*   k_idx   = (const int*)d_in[5];

    int nq      = in_sizes[5];                    // k_indices has N_Q elements
    int n_nodes = in_sizes[3] / H_DIM;            // deg_pos is [N][H]
    if (n_nodes > MAX_NODES) n_nodes = MAX_NODES; // scratch capacity guard

    int tblocks = (n_nodes + TILE_N - 1) / TILE_N;
    transpose_fold_kernel<<<tblocks, 256>>>(phi_pos, phi_neg, deg_pos, deg_neg,
                                            n_nodes);

    int total   = nq * H_DIM;
    int gblocks = (total + 255) / 256;
    gather_dot_kernel<<<gblocks, 256>>>(q_phi, k_idx, (float*)d_out, nq);
}

// round 6
// speedup vs baseline: 2.9279x; 2.9279x over previous
#include <cuda_runtime.h>
#include <cuda_fp16.h>
#include <cstdint>

// Problem constants (fixed-shape problem: H=8, MH=8, N_NODES=500000)
#define H_DIM 8
#define MH_DIM 8
#define FEAT 64              // H*MH per sign
#define REC 128              // 2 signs * FEAT values per node record
#define MAX_NODES 500000

// Node-major scratch in fp16: [node][sign][h][mh], 256B per node,
// deg-normalization folded in. uint4 type guarantees 16B alignment.
__device__ uint4 g_pk_raw[(size_t)MAX_NODES * REC / 8];

// ---- L2 eviction-priority helpers (cache_hint form: legal at any width) ----
__device__ __forceinline__ uint64_t mk_evict_last_policy() {
    uint64_t pol;
    asm("createpolicy.fractional.L2::evict_last.b64 %0, 1.0;" : "=l"(pol));
    return pol;
}
__device__ __forceinline__ void st_hint_b32(void* p, unsigned v, uint64_t pol) {
    asm volatile("st.global.L2::cache_hint.b32 [%0], %1, %2;"
                 :: "l"(p), "r"(v), "l"(pol));
}
__device__ __forceinline__ uint4 ld_hint_v4(const void* p, uint64_t pol) {
    uint4 r;
    asm volatile("ld.global.L2::cache_hint.v4.u32 {%0,%1,%2,%3}, [%4], %5;"
                 : "=r"(r.x), "=r"(r.y), "=r"(r.z), "=r"(r.w)
                 : "l"(p), "l"(pol));
    return r;
}

// ---------------------------------------------------------------------------
// Kernel 1: transpose [s][h][mh][N] (feature-major) -> [N][s][h][mh] fp16,
// multiplying by 1/max(deg,1) on the fly.
// Block: 256 threads handles a tile of 32 nodes x 128 features.
// (R3-proven structure: conflict-free smem in both phases.)
// ---------------------------------------------------------------------------
__global__ __launch_bounds__(256) void transpose_fold_kernel(
    const float* __restrict__ phi_pos,
    const float* __restrict__ phi_neg,
    const float* __restrict__ deg_pos,
    const float* __restrict__ deg_neg,
    int n_nodes)
{
    __shared__ float tile[32][REC + 1];  // [node][feat], stride 129: conflict-free
    __shared__ float inv[2][32][H_DIM];  // 1/max(deg,1) per (sign, node, head)

    const int k0 = blockIdx.x * 32;
    const int t  = threadIdx.x;
    const uint64_t pol = mk_evict_last_policy();

    // Load deg tiles (contiguous) and invert with clamp. Streaming loads.
    #pragma unroll
    for (int it = 0; it < 2; ++it) {
        int idx  = t + it * 256;          // 0..511 : s*256 + node*8 + h
        int s    = idx >> 8;
        int node = (idx >> 3) & 31;
        int h    = idx & 7;
        int k    = k0 + node;
        float d  = 1.0f;
        if (k < n_nodes) {
            const float* dp = s ? deg_neg : deg_pos;
            d = __ldcs(dp + (size_t)k * H_DIM + h);
        }
        inv[s][node][h] = 1.0f / fmaxf(d, 1.0f);
    }

    // Coalesced loads along node axis: 128 feature-rows x 32 nodes.
    // Lanes consecutive kk, smem stride 129 words -> conflict-free.
    #pragma unroll
    for (int it = 0; it < 16; ++it) {
        int l  = t + it * 256;
        int r  = l >> 5;        // feature row 0..127
        int kk = l & 31;        // node within tile
        int k  = k0 + kk;
        int s  = r >> 6;
        int f  = r & 63;        // h*8+mh
        float v = 0.0f;
        if (k < n_nodes) {
            const float* src = s ? phi_neg : phi_pos;
            v = __ldcs(src + (size_t)f * n_nodes + k);   // stream-once
        }
        tile[kk][r] = v;
    }
    __syncthreads();

    // Convert+scale+store as half2 with evict_last hint (keep scratch in L2).
    __half2* gp = reinterpret_cast<__half2*>(g_pk_raw);
    #pragma unroll
    for (int it = 0; it < 8; ++it) {
        int p     = t + it * 256;
        int node  = p >> 6;
        int fpair = p & 63;
        int k     = k0 + node;
        if (k < n_nodes) {
            int f0 = fpair * 2;              // even; f0,f0+1 share sign & head
            int s  = f0 >> 6;
            int h  = (f0 >> 3) & 7;
            float sc = inv[s][node][h];
            float v0 = tile[node][f0];
            float v1 = tile[node][f0 + 1];
            __half2 hv = __floats2half2_rn(v0 * sc, v1 * sc);
            unsigned u;
            __builtin_memcpy(&u, &hv, 4);
            st_hint_b32(gp + (size_t)k * (REC / 2) + fpair, u, pol);
        }
    }
}

// ---------------------------------------------------------------------------
// Kernel 2: gather + dot. 8 threads per query; thread j handles head j for
// both signs. Gathers are 16B loads (evict_last hint) from 256B fp16 records.
// Streaming data (q, idx) uses evict-first; out uses streaming stores.
// out layout: [pos: nq*8][neg: nq*8]
// ---------------------------------------------------------------------------
__global__ __launch_bounds__(256) void gather_dot_kernel(
    const float* __restrict__ q_phi,
    const int*   __restrict__ k_indices,
    float* __restrict__ out,
    int nq)
{
    int t = blockIdx.x * blockDim.x + threadIdx.x;
    int i = t >> 3;
    if (i >= nq) return;
    int h = t & 7;

    const uint64_t pol = mk_evict_last_policy();

    int k = __ldcs(k_indices + i);  // broadcast across the 8-thread group

    const float4* qp = reinterpret_cast<const float4*>(
        q_phi + (size_t)i * FEAT + h * MH_DIM);
    float4 q0 = __ldcs(qp);
    float4 q1 = __ldcs(qp + 1);

    // Record = 16 uint4 (256B). pos: chunks [0..7], neg: chunks [8..15].
    const uint4* rec = g_pk_raw + (size_t)k * (REC / 8);
    uint4 pr = ld_hint_v4(rec + h, pol);
    uint4 nr = ld_hint_v4(rec + 8 + h, pol);

    const __half2* ph = reinterpret_cast<const __half2*>(&pr);
    const __half2* nh = reinterpret_cast<const __half2*>(&nr);

    float2 p0 = __half22float2(ph[0]);
    float2 p1 = __half22float2(ph[1]);
    float2 p2 = __half22float2(ph[2]);
    float2 p3 = __half22float2(ph[3]);
    float2 n0 = __half22float2(nh[0]);
    float2 n1 = __half22float2(nh[1]);
    float2 n2 = __half22float2(nh[2]);
    float2 n3 = __half22float2(nh[3]);

    float dp = q0.x * p0.x + q0.y * p0.y + q0.z * p1.x + q0.w * p1.y
             + q1.x * p2.x + q1.y * p2.y + q1.z * p3.x + q1.w * p3.y;
    float dn = q0.x * n0.x + q0.y * n0.y + q0.z * n1.x + q0.w * n1.y
             + q1.x * n2.x + q1.y * n2.y + q1.z * n3.x + q1.w * n3.y;

    __stcs(out + (size_t)i * H_DIM + h, dp);
    __stcs(out + (size_t)nq * H_DIM + (size_t)i * H_DIM + h, dn);
}

extern "C" void kernel_launch(void* const* d_in, const int* in_sizes, int n_in,
                              void* d_out, int out_size)
{
    const float* q_phi   = (const float*)d_in[0];
    const float* phi_pos = (const float*)d_in[1];
    const float* phi_neg = (const float*)d_in[2];
    const float* deg_pos = (const float*)d_in[3];
    const float* deg_neg = (const float*)d_in[4];
    const int*   k_idx   = (const int*)d_in[5];

    int nq      = in_sizes[5];                    // k_indices has N_Q elements
    int n_nodes = in_sizes[3] / H_DIM;            // deg_pos is [N][H]
    if (n_nodes > MAX_NODES) n_nodes = MAX_NODES; // scratch capacity guard

    int tblocks = (n_nodes + 31) / 32;
    transpose_fold_kernel<<<tblocks, 256>>>(phi_pos, phi_neg, deg_pos, deg_neg,
                                            n_nodes);

    int total   = nq * H_DIM;
    int gblocks = (total + 255) / 256;
    gather_dot_kernel<<<gblocks, 256>>>(q_phi, k_idx, (float*)d_out, nq);
}

// round 7
// speedup vs baseline: 2.9623x; 1.0117x over previous
#include <cuda_runtime.h>
#include <cuda_fp16.h>
#include <cstdint>

// Problem constants (fixed-shape problem: H=8, MH=8, N_NODES=500000)
#define H_DIM 8
#define MH_DIM 8
#define FEAT 64              // H*MH per sign
#define REC 128              // 2 signs * FEAT values per node record
#define MAX_NODES 500000
#define TILE_N 64            // nodes per transpose tile

// Node-major scratch in fp16: [node][sign][h][mh], 256B per node,
// deg-normalization folded in. uint4 type guarantees 16B alignment.
__device__ uint4 g_pk_raw[(size_t)MAX_NODES * REC / 8];

// ---- L2 eviction-priority helpers (cache_hint form) ----
__device__ __forceinline__ uint64_t mk_evict_last_policy() {
    uint64_t pol;
    asm("createpolicy.fractional.L2::evict_last.b64 %0, 1.0;" : "=l"(pol));
    return pol;
}
__device__ __forceinline__ void st_hint_v4(void* p, uint4 v, uint64_t pol) {
    asm volatile("st.global.L2::cache_hint.v4.b32 [%0], {%1,%2,%3,%4}, %5;"
                 :: "l"(p), "r"(v.x), "r"(v.y), "r"(v.z), "r"(v.w), "l"(pol));
}
__device__ __forceinline__ uint4 ld_hint_v4(const void* p, uint64_t pol) {
    uint4 r;
    asm volatile("ld.global.L2::cache_hint.v4.u32 {%0,%1,%2,%3}, [%4], %5;"
                 : "=r"(r.x), "=r"(r.y), "=r"(r.z), "=r"(r.w)
                 : "l"(p), "l"(pol));
    return r;
}

// Swizzled byte offset of (feat f, node n) in the 128x64 float tile.
// Row = 256B. XOR bits[6:4] with bits[9:7]^bits[13:11] so that BOTH the
// feat-row bits and the output-chunk bits (f>>3, stride 2KB) decorrelate
// the bank index -> conflict-free phase-1 stores, <=2-way phase-2 reads.
__device__ __forceinline__ int sw_byte(int f, int n) {
    int off = f * 256 + n * 4;
    int x = ((off >> 7) ^ (off >> 11)) & 7;
    return off ^ (x << 4);
}

// ---------------------------------------------------------------------------
// Kernel 1: transpose [s][h][mh][N] -> [N][s][h][mh] fp16, folding 1/max(deg,1).
// Block: 256 threads, tile 64 nodes x 128 features.
// Phase 1: float4 loads along node axis -> swizzled feature-major smem.
// Phase 2: transpose-read from smem (2-way max), scale, convert, uint4 stores.
// ---------------------------------------------------------------------------
__global__ __launch_bounds__(256) void transpose_fold_kernel(
    const float* __restrict__ phi_pos,
    const float* __restrict__ phi_neg,
    const float* __restrict__ deg_pos,
    const float* __restrict__ deg_neg,
    int n_nodes)
{
    __shared__ __align__(16) char tile_raw[128 * 256];   // 32KB: 128 feats x 64 nodes fp32
    __shared__ float inv[2][TILE_N][H_DIM];              // 4KB

    const int k0 = blockIdx.x * TILE_N;
    const int t  = threadIdx.x;
    const uint64_t pol = mk_evict_last_policy();
    const bool full = (k0 + TILE_N <= n_nodes) && ((n_nodes & 3) == 0);

    // ---- inv table: 2*64*8 = 1024 values ----
    #pragma unroll
    for (int it = 0; it < 4; ++it) {
        int idx  = t + it * 256;            // s*512 + node*8 + h
        int s    = idx >> 9;
        int node = (idx >> 3) & 63;
        int h    = idx & 7;
        int k    = k0 + node;
        float d  = 1.0f;
        if (k < n_nodes) {
            const float* dp = s ? deg_neg : deg_pos;
            d = __ldcs(dp + (size_t)k * H_DIM + h);
        }
        inv[s][node][h] = 1.0f / fmaxf(d, 1.0f);
    }

    // ---- phase 1: load 128 feat-rows x 64 nodes ----
    if (full) {
        #pragma unroll
        for (int it = 0; it < 8; ++it) {
            int l = t + it * 256;           // 0..2047
            int r = l >> 4;                 // feat row 0..127
            int g = l & 15;                 // float4 group (4 nodes)
            int s = r >> 6;
            int f = r & 63;
            const float* src = s ? phi_neg : phi_pos;
            float4 v = __ldcs(reinterpret_cast<const float4*>(
                src + (size_t)f * n_nodes + k0 + 4 * g));
            *reinterpret_cast<float4*>(tile_raw + sw_byte(r, 4 * g)) = v;
        }
    } else {
        #pragma unroll 4
        for (int it = 0; it < 32; ++it) {
            int l  = t + it * 256;          // 128*64 = 8192 elements
            int r  = l >> 6;
            int kk = l & 63;
            int k  = k0 + kk;
            int s  = r >> 6;
            int f  = r & 63;
            float v = 0.0f;
            if (k < n_nodes) {
                const float* src = s ? phi_neg : phi_pos;
                v = __ldcs(src + (size_t)f * n_nodes + k);
            }
            *reinterpret_cast<float*>(tile_raw + sw_byte(r, kk)) = v;
        }
    }
    __syncthreads();

    // ---- phase 2: 64 nodes x 16 chunks; chunk c = feats 8c..8c+7 ----
    #pragma unroll
    for (int it = 0; it < 4; ++it) {
        int l    = t + it * 256;            // 0..1023
        int node = l >> 4;
        int c    = l & 15;
        int k    = k0 + node;
        if (k < n_nodes) {
            int s = c >> 3;
            int h = c & 7;
            float sc = inv[s][node][h];
            __half2 hh[4];
            #pragma unroll
            for (int j = 0; j < 8; j += 2) {
                float a = *reinterpret_cast<const float*>(
                              tile_raw + sw_byte(8 * c + j, node)) * sc;
                float b = *reinterpret_cast<const float*>(
                              tile_raw + sw_byte(8 * c + j + 1, node)) * sc;
                hh[j >> 1] = __floats2half2_rn(a, b);
            }
            uint4 val;
            __builtin_memcpy(&val, hh, 16);
            st_hint_v4(g_pk_raw + (size_t)k * (REC / 8) + c, val, pol);
        }
    }
}

// ---------------------------------------------------------------------------
// Kernel 2: gather + dot (R6-proven). 8 threads per query; thread j = head j.
// out layout: [pos: nq*8][neg: nq*8]
// ---------------------------------------------------------------------------
__global__ __launch_bounds__(256) void gather_dot_kernel(
    const float* __restrict__ q_phi,
    const int*   __restrict__ k_indices,
    float* __restrict__ out,
    int nq)
{
    int t = blockIdx.x * blockDim.x + threadIdx.x;
    int i = t >> 3;
    if (i >= nq) return;
    int h = t & 7;

    const uint64_t pol = mk_evict_last_policy();

    int k = __ldcs(k_indices + i);

    const float4* qp = reinterpret_cast<const float4*>(
        q_phi + (size_t)i * FEAT + h * MH_DIM);
    float4 q0 = __ldcs(qp);
    float4 q1 = __ldcs(qp + 1);

    const uint4* rec = g_pk_raw + (size_t)k * (REC / 8);
    uint4 pr = ld_hint_v4(rec + h, pol);
    uint4 nr = ld_hint_v4(rec + 8 + h, pol);

    const __half2* ph = reinterpret_cast<const __half2*>(&pr);
    const __half2* nh = reinterpret_cast<const __half2*>(&nr);

    float2 p0 = __half22float2(ph[0]);
    float2 p1 = __half22float2(ph[1]);
    float2 p2 = __half22float2(ph[2]);
    float2 p3 = __half22float2(ph[3]);
    float2 n0 = __half22float2(nh[0]);
    float2 n1 = __half22float2(nh[1]);
    float2 n2 = __half22float2(nh[2]);
    float2 n3 = __half22float2(nh[3]);

    float dp = q0.x * p0.x + q0.y * p0.y + q0.z * p1.x + q0.w * p1.y
             + q1.x * p2.x + q1.y * p2.y + q1.z * p3.x + q1.w * p3.y;
    float dn = q0.x * n0.x + q0.y * n0.y + q0.z * n1.x + q0.w * n1.y
             + q1.x * n2.x + q1.y * n2.y + q1.z * n3.x + q1.w * n3.y;

    __stcs(out + (size_t)i * H_DIM + h, dp);
    __stcs(out + (size_t)nq * H_DIM + (size_t)i * H_DIM + h, dn);
}

extern "C" void kernel_launch(void* const* d_in, const int* in_sizes, int n_in,
                              void* d_out, int out_size)
{
    const float* q_phi   = (const float*)d_in[0];
    const float* phi_pos = (const float*)d_in[1];
    const float* phi_neg = (const float*)d_in[2];
    const float* deg_pos = (const float*)d_in[3];
    const float* deg_neg = (const float*)d_in[4];
    const int*   k_idx   = (const int*)d_in[5];

    int nq      = in_sizes[5];                    // k_indices has N_Q elements
    int n_nodes = in_sizes[3] / H_DIM;            // deg_pos is [N][H]
    if (n_nodes > MAX_NODES) n_nodes = MAX_NODES; // scratch capacity guard

    int tblocks = (n_nodes + TILE_N - 1) / TILE_N;
    transpose_fold_kernel<<<tblocks, 256>>>(phi_pos, phi_neg, deg_pos, deg_neg,
                                            n_nodes);

    int total   = nq * H_DIM;
    int gblocks = (total + 255) / 256;
    gather_dot_kernel<<<gblocks, 256>>>(q_phi, k_idx, (float*)d_out, nq);
}